// round 4
// baseline (speedup 1.0000x reference)
#include <cuda_runtime.h>
#include <cuda_bf16.h>
#include <math.h>
#include <stdint.h>

// Sigma_out[b][i][l] = p_i * p_l * ( S[i][l] - q[i] - r[l] + s )
//   p = softmax(mu[b]) ; q = S p ; r = p^T S ; s = p^T S p
// One CTA per batch row. Sigma staged once into smem with a per-row XOR
// swizzle so the row-dot (q), col-dot (r) and output passes are all
// bank-conflict free. All global accesses are scalar 32-bit (proven safe);
// launch_bounds(256,3) caps registers so 3 CTAs fit per SM (RF was the
// occupancy limiter at 128 regs -> 2 CTAs).

#define C 128
#define THREADS 256
#define ELEMS_PER_THREAD (C * C / THREADS)   // 64

__global__ __launch_bounds__(THREADS, 3) void softmax_sigma_kernel(
    const float* __restrict__ mu,       // [B, C]
    const float* __restrict__ Sigma,    // [B, C, C]
    float* __restrict__ mu_out,         // [B, C]
    float* __restrict__ sig_out)        // [B, C, C]
{
    const int b = blockIdx.x;
    const int t = threadIdx.x;

    extern __shared__ float sm[];
    float* Ssm = sm;              // C*C floats; row i, col k at [i*C + (k ^ (i&31))]
    float* p   = sm + C * C;      // 128
    float* qv  = p + C;           // 128  (later reused to hold pq[i] = p_i*(q_i - s))
    float* rv  = qv + C;          // 128
    float* red = rv + C;          // 16 scratch

    const float* Sb = Sigma + (size_t)b * (C * C);
    float*       Ob = sig_out + (size_t)b * (C * C);

    // ---- softmax part 1: warp max of mu[b] (threads 0..127 own one class)
    float x = (t < C) ? mu[b * C + t] : -INFINITY;
    float v = x;
    #pragma unroll
    for (int o = 16; o > 0; o >>= 1)
        v = fmaxf(v, __shfl_xor_sync(0xffffffffu, v, o));
    if (t < C && (t & 31) == 0) red[t >> 5] = v;

    // ---- stage Sigma[b] -> smem. el = t + 256*j: column k = t&127 is FIXED
    // per thread; row i advances by 2 each step. LDG fully coalesced; STS
    // xor-swizzled -> 32 distinct banks per warp.
    {
        const int k   = t & (C - 1);
        int i         = t >> 7;
        const float* g = Sb + t;
        #pragma unroll
        for (int j = 0; j < ELEMS_PER_THREAD; ++j) {
            Ssm[i * C + (k ^ (i & 31))] = g[THREADS * j];
            i += 2;
        }
    }

    __syncthreads();
    float m = fmaxf(fmaxf(red[0], red[1]), fmaxf(red[2], red[3]));
    float e = (t < C) ? expf(x - m) : 0.0f;
    v = e;
    #pragma unroll
    for (int o = 16; o > 0; o >>= 1)
        v += __shfl_xor_sync(0xffffffffu, v, o);
    if (t < C && (t & 31) == 0) red[8 + (t >> 5)] = v;
    __syncthreads();

    float denom = red[8] + red[9] + red[10] + red[11];
    if (t < C) {
        float pt = e / denom;
        p[t] = pt;
        mu_out[b * C + t] = pt;
    }
    __syncthreads();

    // ---- q (warps 0-3: one thread per row) and r (warps 4-7: one per col)
    float qacc = 0.0f;
    if (t < C) {
        const int i  = t;
        const int sw = i & 31;
        const float* row = Ssm + i * C;
        #pragma unroll 8
        for (int k = 0; k < C; ++k)
            qacc = fmaf(row[k ^ sw], p[k], qacc);
    } else {
        const int k = t - C;
        float acc = 0.0f;
        #pragma unroll 8
        for (int i2 = 0; i2 < C; ++i2)
            acc = fmaf(Ssm[i2 * C + (k ^ (i2 & 31))], p[i2], acc);
        rv[k] = acc;
    }

    // ---- s = p . q  (only warps 0-3 hold q)
    float sv = (t < C) ? qacc * p[t] : 0.0f;
    #pragma unroll
    for (int o = 16; o > 0; o >>= 1)
        sv += __shfl_xor_sync(0xffffffffu, sv, o);
    if (t < C && (t & 31) == 0) red[t >> 5] = sv;
    __syncthreads();
    const float s = red[0] + red[1] + red[2] + red[3];

    // pq[i] = p_i * (q_i - s), stored where qv lived
    if (t < C) qv[t] = p[t] * (qacc - s);
    __syncthreads();

    // ---- output: out[i][k] = p_k * ( p_i*(S[i][k] - r[k]) - pq[i] )
    {
        const int k    = t & (C - 1);
        const float pk = p[k];
        const float rk = rv[k];
        int i          = t >> 7;
        float* o       = Ob + t;
        #pragma unroll
        for (int j = 0; j < ELEMS_PER_THREAD; ++j) {
            float val = Ssm[i * C + (k ^ (i & 31))];
            o[THREADS * j] = pk * (p[i] * (val - rk) - qv[i]);
            i += 2;
        }
    }
}

extern "C" void kernel_launch(void* const* d_in, const int* in_sizes, int n_in,
                              void* d_out, int out_size)
{
    // Identify inputs by size: Sigma is C times larger than mu.
    const float* in0 = (const float*)d_in[0];
    const float* in1 = (const float*)d_in[1];
    const float* mu;
    const float* Sigma;
    int B;
    if (in_sizes[0] <= in_sizes[1]) {
        mu = in0; Sigma = in1; B = in_sizes[0] / C;
    } else {
        mu = in1; Sigma = in0; B = in_sizes[1] / C;
    }

    float* mu_out  = (float*)d_out;               // first B*C elements
    float* sig_out = (float*)d_out + (size_t)B * C;

    const int smem = (C * C + 3 * C + 16) * sizeof(float);
    cudaFuncSetAttribute(softmax_sigma_kernel,
                         cudaFuncAttributeMaxDynamicSharedMemorySize, smem);
    softmax_sigma_kernel<<<B, THREADS, smem>>>(mu, Sigma, mu_out, sig_out);
}

// round 5
// speedup vs baseline: 1.0045x; 1.0045x over previous
#include <cuda_runtime.h>
#include <cuda_bf16.h>
#include <math.h>
#include <stdint.h>

// Sigma_out[b][i][l] = p_i * p_l * ( S[i][l] - q[i] - r[l] + s )
//   p = softmax(mu[b]) ; q = S p ; r = p^T S ; s = p^T S p
// One CTA per batch row. l1tex-wavefront-minimized version:
//   - r computed in registers during the staging pass (no r smem pass)
//   - q pass uses all 256 threads (half-row each)
//   - 16-element global prefetch hides the softmax latency bubble
// Sigma lives in smem with per-row XOR swizzle: row i, col k at
// [i*C + (k ^ (i&31))] -> staging STS, q LDS and output LDS are all
// bank-conflict free. All global accesses are scalar 32-bit.

#define C 128
#define THREADS 256
#define EPT 64          // elements per thread of Sigma
#define PF 16           // prefetched elements (registers)

__global__ __launch_bounds__(THREADS, 3) void softmax_sigma_kernel(
    const float* __restrict__ mu,       // [B, C]
    const float* __restrict__ Sigma,    // [B, C, C]
    float* __restrict__ mu_out,         // [B, C]
    float* __restrict__ sig_out)        // [B, C, C]
{
    const int b = blockIdx.x;
    const int t = threadIdx.x;
    const int k = t & (C - 1);          // fixed column for this thread
    const int c = t >> 7;               // 0 or 1

    extern __shared__ float sm[];
    float* Ssm   = sm;                  // 16384 (swizzled Sigma)
    float* psh   = sm + C * C;          // 128  softmax p
    float* pq    = psh + C;             // 128  p_i*(q_i - s)
    float* rtmp  = pq + C;              // 256  r partials (2 per k)
    float* qpart = rtmp + 2 * C;        // 256  q partials (2 per i)
    float* red   = qpart + 2 * C;       // 16   reduction scratch

    const float* Sb = Sigma + (size_t)b * (C * C);
    float*       Ob = sig_out + (size_t)b * (C * C);
    const float* g  = Sb + t;

    // ---- prefetch first PF Sigma values (LDGs in flight during softmax)
    float pf[PF];
    #pragma unroll
    for (int j = 0; j < PF; ++j) pf[j] = g[THREADS * j];

    // ---- softmax over mu[b] (threads 0..127 own one class)
    float x = (t < C) ? mu[b * C + t] : -INFINITY;
    float v = x;
    #pragma unroll
    for (int o = 16; o > 0; o >>= 1)
        v = fmaxf(v, __shfl_xor_sync(0xffffffffu, v, o));
    if (t < C && (t & 31) == 0) red[t >> 5] = v;
    __syncthreads();
    float m = fmaxf(fmaxf(red[0], red[1]), fmaxf(red[2], red[3]));
    float e = (t < C) ? expf(x - m) : 0.0f;
    v = e;
    #pragma unroll
    for (int o = 16; o > 0; o >>= 1)
        v += __shfl_xor_sync(0xffffffffu, v, o);
    if (t < C && (t & 31) == 0) red[8 + (t >> 5)] = v;
    __syncthreads();
    float denom = red[8] + red[9] + red[10] + red[11];
    if (t < C) {
        float pt = e / denom;
        psh[t] = pt;
        mu_out[b * C + t] = pt;
    }
    __syncthreads();

    // ---- staging pass + r accumulation (k fixed per thread)
    // rows i = c, c+2, c+4, ... ; p[i] is a warp-uniform broadcast LDS.
    {
        float racc = 0.0f;
        int i = c;
        #pragma unroll
        for (int j = 0; j < EPT; ++j) {
            float val = (j < PF) ? pf[j] : g[THREADS * j];
            Ssm[i * C + (k ^ (i & 31))] = val;
            racc = fmaf(val, psh[i], racc);
            i += 2;
        }
        rtmp[t] = racc;   // rv[k] = rtmp[k] + rtmp[k+128]
    }
    __syncthreads();

    // ---- q pass: thread t handles row i = t&127, k-range [64c, 64c+64)
    {
        const int i  = k;                 // row index
        const int sw = i & 31;
        const float* row = Ssm + i * C;
        float acc = 0.0f;
        #pragma unroll 8
        for (int kk = 0; kk < 64; ++kk) {
            int kc = 64 * c + kk;         // warp-uniform
            acc = fmaf(row[kc ^ sw], psh[kc], acc);
        }
        qpart[t] = acc;   // q[i] = qpart[i] + qpart[i+128]
    }
    __syncthreads();

    // ---- s = p . q ; pq[i] = p_i*(q_i - s)
    float qi = (t < C) ? (qpart[t] + qpart[t + C]) : 0.0f;
    float sv = (t < C) ? psh[t] * qi : 0.0f;
    #pragma unroll
    for (int o = 16; o > 0; o >>= 1)
        sv += __shfl_xor_sync(0xffffffffu, sv, o);
    if (t < C && (t & 31) == 0) red[t >> 5] = sv;
    __syncthreads();
    const float s = red[0] + red[1] + red[2] + red[3];
    if (t < C) pq[t] = psh[t] * (qi - s);
    __syncthreads();

    // ---- output: out[i][k] = p_k * ( p_i*(S[i][k] - r_k) - pq[i] )
    {
        const float pk = psh[k];
        const float rk = rtmp[k] + rtmp[k + C];
        int i = c;
        float* o = Ob + t;
        #pragma unroll
        for (int j = 0; j < EPT; ++j) {
            float val = Ssm[i * C + (k ^ (i & 31))];
            o[THREADS * j] = pk * (psh[i] * (val - rk) - pq[i]);
            i += 2;
        }
    }
}

extern "C" void kernel_launch(void* const* d_in, const int* in_sizes, int n_in,
                              void* d_out, int out_size)
{
    // Identify inputs by size: Sigma is C times larger than mu.
    const float* in0 = (const float*)d_in[0];
    const float* in1 = (const float*)d_in[1];
    const float* mu;
    const float* Sigma;
    int B;
    if (in_sizes[0] <= in_sizes[1]) {
        mu = in0; Sigma = in1; B = in_sizes[0] / C;
    } else {
        mu = in1; Sigma = in0; B = in_sizes[1] / C;
    }

    float* mu_out  = (float*)d_out;               // first B*C elements
    float* sig_out = (float*)d_out + (size_t)B * C;

    const int smem = (C * C + 2 * C + 2 * (2 * C) + 16) * sizeof(float);
    cudaFuncSetAttribute(softmax_sigma_kernel,
                         cudaFuncAttributeMaxDynamicSharedMemorySize, smem);
    softmax_sigma_kernel<<<B, THREADS, smem>>>(mu, Sigma, mu_out, sig_out);
}